// round 9
// baseline (speedup 1.0000x reference)
#include <cuda_runtime.h>
#include <math.h>
#include <stdint.h>

#define HEADS 8
#define AGENTS 49
#define WIN 32
#define BATCH 32
#define NTOK 1024
#define CH 256
#define HD 32
#define SCALE 0.17677669529663687f  // 32^-0.5

// ---------------- scratch (device globals; no runtime allocation) -----------
__device__ float g_q[BATCH*HEADS*NTOK*HD];    // (b,h,i,d)
__device__ float g_k[BATCH*HEADS*NTOK*HD];
__device__ float g_v[BATCH*HEADS*NTOK*HD];
__device__ float g_ah[BATCH*HEADS*AGENTS*HD]; // agent tokens, head layout
__device__ float g_pb[HEADS*AGENTS*NTOK];     // agent-attn position bias [h][a][i]
__device__ float g_ab[HEADS*AGENTS*NTOK];     // q-attn position bias, TRANSPOSED [h][a][i]
__device__ float g_av[BATCH*HEADS*AGENTS*HD]; // agent_v
__device__ float g_attn[BATCH*NTOK*CH];       // attention out + dwc (b,i,c)

__constant__ int c_starts[7] = {0,4,9,13,18,22,27};
__constant__ int c_ends[7]   = {5,10,14,19,23,28,32};

// ---------------- async copy helpers ------------------------------------------
__device__ __forceinline__ void cp16(void* smem, const void* gmem) {
    uint32_t sa = (uint32_t)__cvta_generic_to_shared(smem);
    asm volatile("cp.async.cg.shared.global [%0], [%1], 16;" :: "r"(sa), "l"(gmem));
}
__device__ __forceinline__ void cp_commit() {
    asm volatile("cp.async.commit_group;");
}
template<int N>
__device__ __forceinline__ void cp_wait() {
    asm volatile("cp.async.wait_group %0;" :: "n"(N));
}

__device__ __forceinline__ uint32_t f2tf32(float f) {
    uint32_t r;
    asm("cvt.rna.tf32.f32 %0, %1;" : "=r"(r) : "f"(f));
    return r;
}

__device__ __forceinline__ void mma_tf32(float* c, const uint32_t* a, const uint32_t* b) {
    asm volatile(
        "mma.sync.aligned.m16n8k8.row.col.f32.tf32.tf32.f32 "
        "{%0,%1,%2,%3},{%4,%5,%6,%7},{%8,%9},{%0,%1,%2,%3};"
        : "+f"(c[0]), "+f"(c[1]), "+f"(c[2]), "+f"(c[3])
        : "r"(a[0]), "r"(a[1]), "r"(a[2]), "r"(a[3]), "r"(b[0]), "r"(b[1]));
}

// ---------------- tensor-core GEMM (tf32), BM=128 BN=128 BK=32, 256 thr ------
// 2-stage cp.async pipeline (dynamic smem, 72KB); rna-rounded tf32 at reg load
#define GEMM_SMEM_FLOATS (4 * 128 * 36)
template<bool QKV>
__global__ __launch_bounds__(256) void gemm_tc(const float* __restrict__ x,
                                               const float* __restrict__ w,
                                               const float* __restrict__ bias,
                                               float* __restrict__ out) {
    extern __shared__ __align__(16) float gsm[];
    float* As[2] = { gsm,               gsm + 2 * 128 * 36 };
    float* Bs[2] = { gsm + 128 * 36,    gsm + 3 * 128 * 36 };
    const int tid = threadIdx.x;
    const int bm = blockIdx.y, bn = blockIdx.x;
    const int warp = tid >> 5, lane = tid & 31;
    const int g = lane >> 2, t = lane & 3;
    const int wm = warp >> 2, wn = warp & 3;
    const int M = QKV ? (BATCH * NTOK) : (BATCH * 1025);

    const float* aptr[4];
    const float* bptr[4];
    int soff[4];
    #pragma unroll
    for (int i = 0; i < 4; i++) {
        int j = tid + i * 256;
        int row = j >> 3;
        int col4 = (j & 7) << 2;
        soff[i] = row * 36 + col4;
        int gm = bm * 128 + row;
        if (QKV) {
            int b_ = gm >> 10, ii = gm & 1023;
            aptr[i] = x + (size_t)(b_ * 1025 + 1 + ii) * 256 + col4;
        } else {
            if (gm < M) {
                int b_ = gm / 1025, tt = gm % 1025;
                aptr[i] = (tt == 0) ? (x + (size_t)b_ * 1025 * 256 + col4)
                                    : (g_attn + (size_t)(b_ * 1024 + tt - 1) * 256 + col4);
            } else {
                aptr[i] = x + col4;
            }
        }
        bptr[i] = w + (size_t)(bn * 128 + row) * 256 + col4;
    }

    float acc[4][4][4] = {};

    // prefetch chunk 0
    #pragma unroll
    for (int i = 0; i < 4; i++) {
        cp16(&As[0][soff[i]], aptr[i]);
        cp16(&Bs[0][soff[i]], bptr[i]);
    }
    cp_commit();

    for (int kc = 0; kc < 8; kc++) {
        const int cur = kc & 1;
        if (kc < 7) {
            const int nxt = cur ^ 1;
            const int off = (kc + 1) * 32;
            #pragma unroll
            for (int i = 0; i < 4; i++) {
                cp16(&As[nxt][soff[i]], aptr[i] + off);
                cp16(&Bs[nxt][soff[i]], bptr[i] + off);
            }
            cp_commit();
            cp_wait<1>();
        } else {
            cp_wait<0>();
        }
        __syncthreads();

        const float* Ac = As[cur];
        const float* Bc = Bs[cur];
        #pragma unroll
        for (int ks = 0; ks < 4; ks++) {
            const int kb = ks * 8;
            uint32_t af[4][4];
            #pragma unroll
            for (int mt = 0; mt < 4; mt++) {
                int mrow = wm * 64 + mt * 16 + g;
                af[mt][0] = f2tf32(Ac[mrow * 36 + kb + t]);
                af[mt][1] = f2tf32(Ac[(mrow + 8) * 36 + kb + t]);
                af[mt][2] = f2tf32(Ac[mrow * 36 + kb + t + 4]);
                af[mt][3] = f2tf32(Ac[(mrow + 8) * 36 + kb + t + 4]);
            }
            uint32_t bf[4][2];
            #pragma unroll
            for (int nt = 0; nt < 4; nt++) {
                int nrow = wn * 32 + nt * 8 + g;
                bf[nt][0] = f2tf32(Bc[nrow * 36 + kb + t]);
                bf[nt][1] = f2tf32(Bc[nrow * 36 + kb + t + 4]);
            }
            #pragma unroll
            for (int mt = 0; mt < 4; mt++)
                #pragma unroll
                for (int nt = 0; nt < 4; nt++)
                    mma_tf32(acc[mt][nt], af[mt], bf[nt]);
        }
        __syncthreads();
    }

    #pragma unroll
    for (int mt = 0; mt < 4; mt++) {
        #pragma unroll
        for (int nt = 0; nt < 4; nt++) {
            int coln = bn * 128 + wn * 32 + nt * 8 + 2 * t;
            #pragma unroll
            for (int half = 0; half < 2; half++) {
                int row = bm * 128 + wm * 64 + mt * 16 + g + half * 8;
                float v0 = acc[mt][nt][half * 2 + 0];
                float v1 = acc[mt][nt][half * 2 + 1];
                if (QKV) {
                    int b_ = row >> 10, i_ = row & 1023;
                    int tsel = coln >> 8, c_ = coln & 255;
                    int h = c_ >> 5, d = c_ & 31;
                    float* dst = (tsel == 0) ? g_q : (tsel == 1) ? g_k : g_v;
                    *(float2*)&dst[((size_t)(b_ * 8 + h) * 1024 + i_) * 32 + d] =
                        make_float2(v0, v1);
                } else {
                    if (row < M) {
                        *(float2*)&out[(size_t)row * 256 + coln] =
                            make_float2(v0 + bias[coln], v1 + bias[coln + 1]);
                    }
                }
            }
        }
    }
}

// ---------------- adaptive avg pool q -> agents ------------------------------
__global__ void pool_kernel() {
    int idx = blockIdx.x * 256 + threadIdx.x;
    if (idx >= BATCH * AGENTS * CH) return;
    int c = idx & 255;
    int a = (idx >> 8) % 49;
    int b = idx / (49 * 256);
    int ay = a / 7, ax = a % 7;
    int h = c >> 5, d = c & 31;
    const float* base = g_q + (size_t)(b * 8 + h) * 1024 * 32 + d;
    int ys = c_starts[ay], ye = c_ends[ay];
    int xs = c_starts[ax], xe = c_ends[ax];
    float s = 0.f;
    for (int y = ys; y < ye; y++)
        for (int xx = xs; xx < xe; xx++)
            s += base[(y * 32 + xx) * 32];
    s /= (float)((ye - ys) * (xe - xs));
    g_ah[((size_t)(b * 8 + h) * 49 + a) * 32 + d] = s;
}

// ---------------- bilinear 7x7 -> 32x32 (jax half-pixel == clamped bilerp) ---
__device__ __forceinline__ float bilerp7(const float* __restrict__ t, int y, int x) {
    float sy = (y + 0.5f) * 0.21875f - 0.5f;
    float sx = (x + 0.5f) * 0.21875f - 0.5f;
    sy = fminf(fmaxf(sy, 0.f), 6.f);
    sx = fminf(fmaxf(sx, 0.f), 6.f);
    int y0 = (int)sy, x0 = (int)sx;
    int y1 = min(y0 + 1, 6), x1 = min(x0 + 1, 6);
    float fy = sy - (float)y0, fx = sx - (float)x0;
    float v00 = t[y0 * 7 + x0], v01 = t[y0 * 7 + x1];
    float v10 = t[y1 * 7 + x0], v11 = t[y1 * 7 + x1];
    return (1.f - fy) * ((1.f - fx) * v00 + fx * v01)
         + fy * ((1.f - fx) * v10 + fx * v11);
}

__global__ void pb_kernel(const float* __restrict__ an,
                          const float* __restrict__ ahb,
                          const float* __restrict__ awb) {
    int idx = blockIdx.x * 256 + threadIdx.x;
    if (idx >= HEADS * AGENTS * NTOK) return;
    int x = idx & 31, y = (idx >> 5) & 31;
    int a = (idx >> 10) % 49, h = idx / (49 * 1024);
    float v = bilerp7(an + (h * 49 + a) * 49, y, x);
    v += ahb[(h * 49 + a) * 32 + y] + awb[(h * 49 + a) * 32 + x];
    g_pb[idx] = v;
}

// writes TRANSPOSED layout: g_ab[h][a][i]
__global__ void ab_kernel(const float* __restrict__ na,
                          const float* __restrict__ hab,
                          const float* __restrict__ wab) {
    int idx = blockIdx.x * 256 + threadIdx.x;
    if (idx >= HEADS * AGENTS * NTOK) return;
    int i = idx & 1023;
    int a = (idx >> 10) % 49;
    int h = idx / (49 * 1024);
    int y = i >> 5, x = i & 31;
    float v = bilerp7(na + (h * 49 + a) * 49, y, x);
    v += hab[(h * 32 + y) * 49 + a] + wab[(h * 32 + x) * 49 + a];
    g_ab[idx] = v;
}

// ---------------- fused agent attention: softmax(ah@K^T*s + pb) @ V ----------
// grid (2, 256): x = agent-half (25 / 24 agents), y = (b,h); flash online softmax
#define SS_PAD 129
__global__ __launch_bounds__(256) void agent_attn_fused() {
    __shared__ __align__(16) float Vt[128 * 32];
    __shared__ __align__(16) float ahs[25 * 32];
    __shared__ __align__(16) float Ss[25 * SS_PAD];
    __shared__ float m_s[25], l_s[25], scale_s[25];
    const int A0 = blockIdx.x ? 25 : 0;
    const int NA = blockIdx.x ? 24 : 25;
    const int bh = blockIdx.y;
    const int tid = threadIdx.x;
    const int warp = tid >> 5, lane = tid & 31;
    const int h = bh & 7;
    for (int j = tid; j < NA * 32; j += 256) ahs[j] = g_ah[(size_t)bh * 1568 + A0 * 32 + j];
    if (tid < NA) { m_s[tid] = -1e30f; l_s[tid] = 0.f; }
    float acc[4] = {};
    const int half = tid >> 7;
    const int ii = tid & 127;
    const int la0 = half ? 13 : 0;
    const int lan = half ? (NA - 13) : 13;
    __syncthreads();

    for (int it = 0; it < 8; it++) {
        const int i0 = it * 128;
        // load V tile (coalesced)
        {
            const float4* src = (const float4*)(g_v + ((size_t)bh * 1024 + i0) * 32);
            float4* dst4 = (float4*)Vt;
            for (int j = tid; j < 1024; j += 256) dst4[j] = src[j];
        }
        // scores
        {
            __align__(16) float kr[32];
            const float4* krow = (const float4*)(g_k + ((size_t)bh * 1024 + i0 + ii) * 32);
            #pragma unroll
            for (int j = 0; j < 8; j++) ((float4*)kr)[j] = krow[j];
            const float* pbb = g_pb + (size_t)h * 49 * 1024 + (size_t)A0 * 1024 + i0 + ii;
            for (int la = la0; la < la0 + lan; la++) {
                float dot = 0.f;
                #pragma unroll
                for (int d = 0; d < 32; d++) dot += ahs[la * 32 + d] * kr[d];
                Ss[la * SS_PAD + ii] = dot * SCALE + pbb[(size_t)la * 1024];
            }
        }
        __syncthreads();
        // per-agent tile max -> running max + rescale factor
        {
            int a = tid >> 2, q = tid & 3;
            float tm = -1e30f;
            if (a < NA) {
                const float* row = Ss + a * SS_PAD + q * 32;
                #pragma unroll
                for (int k2 = 0; k2 < 32; k2++) tm = fmaxf(tm, row[k2]);
            }
            tm = fmaxf(tm, __shfl_xor_sync(0xffffffffu, tm, 1));
            tm = fmaxf(tm, __shfl_xor_sync(0xffffffffu, tm, 2));
            if (a < NA && q == 0) {
                float mo = m_s[a];
                float mn = fmaxf(mo, tm);
                scale_s[a] = __expf(mo - mn);
                m_s[a] = mn;
            }
        }
        __syncthreads();
        // exp in place + per-agent sum
        {
            int a = tid >> 2, q = tid & 3;
            float ts = 0.f;
            if (a < NA) {
                float mm = m_s[a];
                float* row = Ss + a * SS_PAD + q * 32;
                #pragma unroll
                for (int k2 = 0; k2 < 32; k2++) {
                    float e = __expf(row[k2] - mm);
                    row[k2] = e;
                    ts += e;
                }
            }
            ts += __shfl_xor_sync(0xffffffffu, ts, 1);
            ts += __shfl_xor_sync(0xffffffffu, ts, 2);
            if (a < NA && q == 0) l_s[a] = l_s[a] * scale_s[a] + ts;
        }
        __syncthreads();
        // P @ V accumulate: warp owns local agents (warp + 8r), lane owns d
        {
            #pragma unroll
            for (int r = 0; r < 4; r++) {
                int a = warp + r * 8;
                if (a < NA) acc[r] *= scale_s[a];
            }
            for (int iik = 0; iik < 128; iik++) {
                float v = Vt[iik * 32 + lane];
                #pragma unroll
                for (int r = 0; r < 4; r++) {
                    int a = warp + r * 8;
                    if (a < NA) acc[r] += Ss[a * SS_PAD + iik] * v;
                }
            }
        }
        __syncthreads();
    }

    #pragma unroll
    for (int r = 0; r < 4; r++) {
        int a = warp + r * 8;
        if (a < NA)
            g_av[(size_t)bh * 1568 + (A0 + a) * 32 + lane] = acc[r] / l_s[a];
    }
}

// ---------------- fused q-attn + depthwise conv ------------------------------
// block = (itile, bh), 128 threads = 4 image rows x 32 cols; dynamic smem
#define VROW (34 * 33)
__global__ __launch_bounds__(128) void attn2_dwc_kernel(const float* __restrict__ dwc_w,
                                                        const float* __restrict__ dwc_b) {
    extern __shared__ __align__(16) float sm[];
    float* ahs = sm;
    float* avs = ahs + 1568;
    float* vsm = avs + 1568;
    float* wsm = vsm + 6 * VROW;
    float* bsm = wsm + 288;

    const int bh = blockIdx.y, itile = blockIdx.x, tid = threadIdx.x;
    const int h = bh & 7, b_ = bh >> 3;
    const int i0 = itile * 128;
    const int y0 = itile * 4;
    const int warp = tid >> 5, lane = tid & 31;

    for (int j = tid; j < 1568; j += 128) {
        ahs[j] = g_ah[(size_t)bh * 1568 + j];
        avs[j] = g_av[(size_t)bh * 1568 + j];
    }
    for (int j = tid; j < 288; j += 128) wsm[j] = dwc_w[(h * 32) * 9 + j];
    if (tid < 32) bsm[tid] = dwc_b[h * 32 + tid];
    for (int j = tid; j < 6 * VROW; j += 128) vsm[j] = 0.f;
    __syncthreads();

    // fill v halo: rows y0-1 .. y0+4, padded x in [1,32]
    for (int j = tid; j < 6 * 1024; j += 128) {
        int row = j >> 10;
        int rem = j & 1023;
        int x = rem >> 5, d = rem & 31;
        int gy = y0 - 1 + row;
        if (gy >= 0 && gy < 32)
            vsm[row * VROW + (x + 1) * 33 + d] =
                g_v[((size_t)bh * 1024 + gy * 32 + x) * 32 + d];
    }
    __syncthreads();

    const int i = i0 + tid;
    __align__(16) float q[32];
    const float4* qr = (const float4*)(g_q + ((size_t)bh * 1024 + i) * 32);
    #pragma unroll
    for (int j = 0; j < 8; j++) ((float4*)q)[j] = qr[j];
    const float* abg = g_ab + (size_t)h * 49 * 1024 + i;  // [h][a][i] layout, coalesced per a

    float s[49];
    float m = -1e30f;
    #pragma unroll
    for (int a = 0; a < 49; a++) {
        float dot = 0.f;
        #pragma unroll
        for (int d = 0; d < 32; d++) dot += q[d] * ahs[a * 32 + d];
        s[a] = dot * SCALE + abg[(size_t)a * 1024];
        m = fmaxf(m, s[a]);
    }
    float sum = 0.f;
    #pragma unroll
    for (int a = 0; a < 49; a++) {
        s[a] = __expf(s[a] - m);
        sum += s[a];
    }
    float inv = 1.f / sum;
    __align__(16) float out[32] = {};
    #pragma unroll
    for (int a = 0; a < 49; a++) {
        #pragma unroll
        for (int d = 0; d < 32; d++) out[d] += s[a] * avs[a * 32 + d];
    }

    // depthwise 3x3 on v (zero-padded) + bias, folded into same output
    const float* vrow0 = vsm + warp * VROW + lane * 33;  // (row y-1, x-1) base
    #pragma unroll
    for (int d = 0; d < 32; d++) {
        float sdw = bsm[d];
        #pragma unroll
        for (int dy = 0; dy < 3; dy++) {
            const float* vr = vrow0 + dy * VROW + d;
            const float* wk = wsm + d * 9 + dy * 3;
            sdw += vr[0] * wk[0] + vr[33] * wk[1] + vr[66] * wk[2];
        }
        out[d] = out[d] * inv + sdw;
    }

    float* dst = g_attn + ((size_t)(b_ * 1024 + i) * 256) + h * 32;
    #pragma unroll
    for (int j = 0; j < 8; j++) ((float4*)dst)[j] = ((const float4*)out)[j];
}

// ---------------- launch ------------------------------------------------------
extern "C" void kernel_launch(void* const* d_in, const int* in_sizes, int n_in,
                              void* d_out, int out_size) {
    const float* x      = (const float*)d_in[0];
    const float* qkv_w  = (const float*)d_in[1];
    const float* proj_w = (const float*)d_in[2];
    const float* proj_b = (const float*)d_in[3];
    const float* dwc_w  = (const float*)d_in[4];
    const float* dwc_b  = (const float*)d_in[5];
    const float* an_b   = (const float*)d_in[6];
    const float* ah_b   = (const float*)d_in[7];
    const float* aw_b   = (const float*)d_in[8];
    const float* na_b   = (const float*)d_in[9];
    const float* ha_b   = (const float*)d_in[10];
    const float* wa_b   = (const float*)d_in[11];
    float* out = (float*)d_out;

    const int gemm_smem = GEMM_SMEM_FLOATS * 4;  // 73728 bytes
    cudaFuncSetAttribute(gemm_tc<true>,
                         cudaFuncAttributeMaxDynamicSharedMemorySize, gemm_smem);
    cudaFuncSetAttribute(gemm_tc<false>,
                         cudaFuncAttributeMaxDynamicSharedMemorySize, gemm_smem);
    const int attn2_smem = (1568 + 1568 + 6 * VROW + 288 + 32) * 4;
    cudaFuncSetAttribute(attn2_dwc_kernel,
                         cudaFuncAttributeMaxDynamicSharedMemorySize, attn2_smem);

    gemm_tc<true><<<dim3(6, 256), 256, gemm_smem>>>(x, qkv_w, nullptr, nullptr);
    pool_kernel<<<(BATCH * AGENTS * CH + 255) / 256, 256>>>();
    pb_kernel<<<(HEADS * AGENTS * NTOK + 255) / 256, 256>>>(an_b, ah_b, aw_b);
    ab_kernel<<<(HEADS * AGENTS * NTOK + 255) / 256, 256>>>(na_b, ha_b, wa_b);
    agent_attn_fused<<<dim3(2, BATCH * HEADS), 256>>>();
    attn2_dwc_kernel<<<dim3(8, 256), 128, attn2_smem>>>(dwc_w, dwc_b);
    gemm_tc<false><<<dim3(2, 257), 256, gemm_smem>>>(x, proj_w, proj_b, out);
}

// round 10
// speedup vs baseline: 1.0545x; 1.0545x over previous
#include <cuda_runtime.h>
#include <math.h>
#include <stdint.h>

#define HEADS 8
#define AGENTS 49
#define WIN 32
#define BATCH 32
#define NTOK 1024
#define CH 256
#define HD 32
#define SCALE 0.17677669529663687f  // 32^-0.5

// ---------------- scratch (device globals; no runtime allocation) -----------
__device__ float g_q[BATCH*HEADS*NTOK*HD];    // (b,h,i,d)
__device__ float g_k[BATCH*HEADS*NTOK*HD];
__device__ float g_v[BATCH*HEADS*NTOK*HD];
__device__ float g_ah[BATCH*HEADS*AGENTS*HD]; // agent tokens, head layout
__device__ float g_pb[HEADS*AGENTS*NTOK];     // agent-attn position bias [h][a][i]
__device__ float g_ab[HEADS*AGENTS*NTOK];     // q-attn position bias, TRANSPOSED [h][a][i]
__device__ float g_av[BATCH*HEADS*AGENTS*HD]; // agent_v
__device__ float g_attn[BATCH*NTOK*CH];       // attention out + dwc (b,i,c)

__constant__ int c_starts[7] = {0,4,9,13,18,22,27};
__constant__ int c_ends[7]   = {5,10,14,19,23,28,32};

// ---------------- tf32 helpers ----------------------------------------------
__device__ __forceinline__ uint32_t f2tf32(float f) {
    uint32_t r;
    asm("cvt.rna.tf32.f32 %0, %1;" : "=r"(r) : "f"(f));
    return r;
}

__device__ __forceinline__ void mma_tf32(float* c, const uint32_t* a, const uint32_t* b) {
    asm volatile(
        "mma.sync.aligned.m16n8k8.row.col.f32.tf32.tf32.f32 "
        "{%0,%1,%2,%3},{%4,%5,%6,%7},{%8,%9},{%0,%1,%2,%3};"
        : "+f"(c[0]), "+f"(c[1]), "+f"(c[2]), "+f"(c[3])
        : "r"(a[0]), "r"(a[1]), "r"(a[2]), "r"(a[3]), "r"(b[0]), "r"(b[1]));
}

// ---------------- tensor-core GEMM (tf32), BM=128 BN=128 BK=32, 256 thr ------
// R6-proven version: static smem, single-buffer, cvt at smem store
template<bool QKV>
__global__ __launch_bounds__(256) void gemm_tc(const float* __restrict__ x,
                                               const float* __restrict__ w,
                                               const float* __restrict__ bias,
                                               float* __restrict__ out) {
    __shared__ __align__(16) uint32_t As[128 * 36];
    __shared__ __align__(16) uint32_t Bs[128 * 36];
    const int tid = threadIdx.x;
    const int bm = blockIdx.y, bn = blockIdx.x;
    const int warp = tid >> 5, lane = tid & 31;
    const int g = lane >> 2, t = lane & 3;
    const int wm = warp >> 2, wn = warp & 3;
    const int M = QKV ? (BATCH * NTOK) : (BATCH * 1025);

    const float* aptr[4];
    const float* bptr[4];
    int soff[4];
    #pragma unroll
    for (int i = 0; i < 4; i++) {
        int j = tid + i * 256;
        int row = j >> 3;
        int col4 = (j & 7) << 2;
        soff[i] = row * 36 + col4;
        int gm = bm * 128 + row;
        if (QKV) {
            int b_ = gm >> 10, ii = gm & 1023;
            aptr[i] = x + (size_t)(b_ * 1025 + 1 + ii) * 256 + col4;
        } else {
            if (gm < M) {
                int b_ = gm / 1025, tt = gm % 1025;
                aptr[i] = (tt == 0) ? (x + (size_t)b_ * 1025 * 256 + col4)
                                    : (g_attn + (size_t)(b_ * 1024 + tt - 1) * 256 + col4);
            } else {
                aptr[i] = x + col4;
            }
        }
        bptr[i] = w + (size_t)(bn * 128 + row) * 256 + col4;
    }

    float acc[4][4][4] = {};

    for (int kc = 0; kc < 256; kc += 32) {
        #pragma unroll
        for (int i = 0; i < 4; i++) {
            float4 av = *(const float4*)(aptr[i] + kc);
            float4 bv = *(const float4*)(bptr[i] + kc);
            uint4 au = make_uint4(f2tf32(av.x), f2tf32(av.y), f2tf32(av.z), f2tf32(av.w));
            uint4 bu = make_uint4(f2tf32(bv.x), f2tf32(bv.y), f2tf32(bv.z), f2tf32(bv.w));
            *(uint4*)&As[soff[i]] = au;
            *(uint4*)&Bs[soff[i]] = bu;
        }
        __syncthreads();
        #pragma unroll
        for (int ks = 0; ks < 4; ks++) {
            const int kb = ks * 8;
            uint32_t af[4][4];
            #pragma unroll
            for (int mt = 0; mt < 4; mt++) {
                int mrow = wm * 64 + mt * 16 + g;
                af[mt][0] = As[mrow * 36 + kb + t];
                af[mt][1] = As[(mrow + 8) * 36 + kb + t];
                af[mt][2] = As[mrow * 36 + kb + t + 4];
                af[mt][3] = As[(mrow + 8) * 36 + kb + t + 4];
            }
            uint32_t bf[4][2];
            #pragma unroll
            for (int nt = 0; nt < 4; nt++) {
                int nrow = wn * 32 + nt * 8 + g;
                bf[nt][0] = Bs[nrow * 36 + kb + t];
                bf[nt][1] = Bs[nrow * 36 + kb + t + 4];
            }
            #pragma unroll
            for (int mt = 0; mt < 4; mt++)
                #pragma unroll
                for (int nt = 0; nt < 4; nt++)
                    mma_tf32(acc[mt][nt], af[mt], bf[nt]);
        }
        __syncthreads();
    }

    #pragma unroll
    for (int mt = 0; mt < 4; mt++) {
        #pragma unroll
        for (int nt = 0; nt < 4; nt++) {
            int coln = bn * 128 + wn * 32 + nt * 8 + 2 * t;
            #pragma unroll
            for (int half = 0; half < 2; half++) {
                int row = bm * 128 + wm * 64 + mt * 16 + g + half * 8;
                float v0 = acc[mt][nt][half * 2 + 0];
                float v1 = acc[mt][nt][half * 2 + 1];
                if (QKV) {
                    int b_ = row >> 10, i_ = row & 1023;
                    int tsel = coln >> 8, c_ = coln & 255;
                    int h = c_ >> 5, d = c_ & 31;
                    float* dst = (tsel == 0) ? g_q : (tsel == 1) ? g_k : g_v;
                    *(float2*)&dst[((size_t)(b_ * 8 + h) * 1024 + i_) * 32 + d] =
                        make_float2(v0, v1);
                } else {
                    if (row < M) {
                        *(float2*)&out[(size_t)row * 256 + coln] =
                            make_float2(v0 + bias[coln], v1 + bias[coln + 1]);
                    }
                }
            }
        }
    }
}

// ---------------- adaptive avg pool q -> agents ------------------------------
__global__ void pool_kernel() {
    int idx = blockIdx.x * 256 + threadIdx.x;
    if (idx >= BATCH * AGENTS * CH) return;
    int c = idx & 255;
    int a = (idx >> 8) % 49;
    int b = idx / (49 * 256);
    int ay = a / 7, ax = a % 7;
    int h = c >> 5, d = c & 31;
    const float* base = g_q + (size_t)(b * 8 + h) * 1024 * 32 + d;
    int ys = c_starts[ay], ye = c_ends[ay];
    int xs = c_starts[ax], xe = c_ends[ax];
    float s = 0.f;
    for (int y = ys; y < ye; y++)
        for (int xx = xs; xx < xe; xx++)
            s += base[(y * 32 + xx) * 32];
    s /= (float)((ye - ys) * (xe - xs));
    g_ah[((size_t)(b * 8 + h) * 49 + a) * 32 + d] = s;
}

// ---------------- bilinear 7x7 -> 32x32 (jax half-pixel == clamped bilerp) ---
__device__ __forceinline__ float bilerp7(const float* __restrict__ t, int y, int x) {
    float sy = (y + 0.5f) * 0.21875f - 0.5f;
    float sx = (x + 0.5f) * 0.21875f - 0.5f;
    sy = fminf(fmaxf(sy, 0.f), 6.f);
    sx = fminf(fmaxf(sx, 0.f), 6.f);
    int y0 = (int)sy, x0 = (int)sx;
    int y1 = min(y0 + 1, 6), x1 = min(x0 + 1, 6);
    float fy = sy - (float)y0, fx = sx - (float)x0;
    float v00 = t[y0 * 7 + x0], v01 = t[y0 * 7 + x1];
    float v10 = t[y1 * 7 + x0], v11 = t[y1 * 7 + x1];
    return (1.f - fy) * ((1.f - fx) * v00 + fx * v01)
         + fy * ((1.f - fx) * v10 + fx * v11);
}

__global__ void pb_kernel(const float* __restrict__ an,
                          const float* __restrict__ ahb,
                          const float* __restrict__ awb) {
    int idx = blockIdx.x * 256 + threadIdx.x;
    if (idx >= HEADS * AGENTS * NTOK) return;
    int x = idx & 31, y = (idx >> 5) & 31;
    int a = (idx >> 10) % 49, h = idx / (49 * 1024);
    float v = bilerp7(an + (h * 49 + a) * 49, y, x);
    v += ahb[(h * 49 + a) * 32 + y] + awb[(h * 49 + a) * 32 + x];
    g_pb[idx] = v;
}

// writes TRANSPOSED layout: g_ab[h][a][i]
__global__ void ab_kernel(const float* __restrict__ na,
                          const float* __restrict__ hab,
                          const float* __restrict__ wab) {
    int idx = blockIdx.x * 256 + threadIdx.x;
    if (idx >= HEADS * AGENTS * NTOK) return;
    int i = idx & 1023;
    int a = (idx >> 10) % 49;
    int h = idx / (49 * 1024);
    int y = i >> 5, x = i & 31;
    float v = bilerp7(na + (h * 49 + a) * 49, y, x);
    v += hab[(h * 32 + y) * 49 + a] + wab[(h * 32 + x) * 49 + a];
    g_ab[idx] = v;
}

// ---------------- fused agent attention: softmax(ah@K^T*s + pb) @ V ----------
// grid (2, 256): x = agent-half (25 / 24 agents), y = (b,h); flash online softmax
#define SS_PAD 129
__global__ __launch_bounds__(256) void agent_attn_fused() {
    __shared__ __align__(16) float Vt[128 * 32];
    __shared__ __align__(16) float ahs[25 * 32];
    __shared__ __align__(16) float Ss[25 * SS_PAD];
    __shared__ float m_s[25], l_s[25], scale_s[25];
    const int A0 = blockIdx.x ? 25 : 0;
    const int NA = blockIdx.x ? 24 : 25;
    const int bh = blockIdx.y;
    const int tid = threadIdx.x;
    const int warp = tid >> 5, lane = tid & 31;
    const int h = bh & 7;
    for (int j = tid; j < NA * 32; j += 256) ahs[j] = g_ah[(size_t)bh * 1568 + A0 * 32 + j];
    if (tid < NA) { m_s[tid] = -1e30f; l_s[tid] = 0.f; }
    float acc[4] = {};
    const int half = tid >> 7;
    const int ii = tid & 127;
    const int la0 = half ? 13 : 0;
    const int lan = half ? (NA - 13) : 13;
    __syncthreads();

    for (int it = 0; it < 8; it++) {
        const int i0 = it * 128;
        // load V tile (coalesced)
        {
            const float4* src = (const float4*)(g_v + ((size_t)bh * 1024 + i0) * 32);
            float4* dst4 = (float4*)Vt;
            for (int j = tid; j < 1024; j += 256) dst4[j] = src[j];
        }
        // scores
        {
            __align__(16) float kr[32];
            const float4* krow = (const float4*)(g_k + ((size_t)bh * 1024 + i0 + ii) * 32);
            #pragma unroll
            for (int j = 0; j < 8; j++) ((float4*)kr)[j] = krow[j];
            const float* pbb = g_pb + (size_t)h * 49 * 1024 + (size_t)A0 * 1024 + i0 + ii;
            for (int la = la0; la < la0 + lan; la++) {
                float dot = 0.f;
                #pragma unroll
                for (int d = 0; d < 32; d++) dot += ahs[la * 32 + d] * kr[d];
                Ss[la * SS_PAD + ii] = dot * SCALE + pbb[(size_t)la * 1024];
            }
        }
        __syncthreads();
        // per-agent tile max -> running max + rescale factor
        {
            int a = tid >> 2, q = tid & 3;
            float tm = -1e30f;
            if (a < NA) {
                const float* row = Ss + a * SS_PAD + q * 32;
                #pragma unroll
                for (int k2 = 0; k2 < 32; k2++) tm = fmaxf(tm, row[k2]);
            }
            tm = fmaxf(tm, __shfl_xor_sync(0xffffffffu, tm, 1));
            tm = fmaxf(tm, __shfl_xor_sync(0xffffffffu, tm, 2));
            if (a < NA && q == 0) {
                float mo = m_s[a];
                float mn = fmaxf(mo, tm);
                scale_s[a] = __expf(mo - mn);
                m_s[a] = mn;
            }
        }
        __syncthreads();
        // exp in place + per-agent sum
        {
            int a = tid >> 2, q = tid & 3;
            float ts = 0.f;
            if (a < NA) {
                float mm = m_s[a];
                float* row = Ss + a * SS_PAD + q * 32;
                #pragma unroll
                for (int k2 = 0; k2 < 32; k2++) {
                    float e = __expf(row[k2] - mm);
                    row[k2] = e;
                    ts += e;
                }
            }
            ts += __shfl_xor_sync(0xffffffffu, ts, 1);
            ts += __shfl_xor_sync(0xffffffffu, ts, 2);
            if (a < NA && q == 0) l_s[a] = l_s[a] * scale_s[a] + ts;
        }
        __syncthreads();
        // P @ V accumulate: warp owns local agents (warp + 8r), lane owns d
        {
            #pragma unroll
            for (int r = 0; r < 4; r++) {
                int a = warp + r * 8;
                if (a < NA) acc[r] *= scale_s[a];
            }
            for (int iik = 0; iik < 128; iik++) {
                float v = Vt[iik * 32 + lane];
                #pragma unroll
                for (int r = 0; r < 4; r++) {
                    int a = warp + r * 8;
                    if (a < NA) acc[r] += Ss[a * SS_PAD + iik] * v;
                }
            }
        }
        __syncthreads();
    }

    #pragma unroll
    for (int r = 0; r < 4; r++) {
        int a = warp + r * 8;
        if (a < NA)
            g_av[(size_t)bh * 1568 + (A0 + a) * 32 + lane] = acc[r] / l_s[a];
    }
}

// ---------------- fused q-attn + depthwise conv ------------------------------
// block = (itile, bh), 128 threads = 4 image rows x 32 cols; dynamic smem
#define VROW (34 * 33)
__global__ __launch_bounds__(128) void attn2_dwc_kernel(const float* __restrict__ dwc_w,
                                                        const float* __restrict__ dwc_b) {
    extern __shared__ __align__(16) float sm[];
    float* ahs = sm;
    float* avs = ahs + 1568;
    float* vsm = avs + 1568;
    float* wsm = vsm + 6 * VROW;
    float* bsm = wsm + 288;

    const int bh = blockIdx.y, itile = blockIdx.x, tid = threadIdx.x;
    const int h = bh & 7, b_ = bh >> 3;
    const int i0 = itile * 128;
    const int y0 = itile * 4;
    const int warp = tid >> 5, lane = tid & 31;

    for (int j = tid; j < 1568; j += 128) {
        ahs[j] = g_ah[(size_t)bh * 1568 + j];
        avs[j] = g_av[(size_t)bh * 1568 + j];
    }
    for (int j = tid; j < 288; j += 128) wsm[j] = dwc_w[(h * 32) * 9 + j];
    if (tid < 32) bsm[tid] = dwc_b[h * 32 + tid];
    for (int j = tid; j < 6 * VROW; j += 128) vsm[j] = 0.f;
    __syncthreads();

    // fill v halo: rows y0-1 .. y0+4, padded x in [1,32]
    for (int j = tid; j < 6 * 1024; j += 128) {
        int row = j >> 10;
        int rem = j & 1023;
        int x = rem >> 5, d = rem & 31;
        int gy = y0 - 1 + row;
        if (gy >= 0 && gy < 32)
            vsm[row * VROW + (x + 1) * 33 + d] =
                g_v[((size_t)bh * 1024 + gy * 32 + x) * 32 + d];
    }
    __syncthreads();

    const int i = i0 + tid;
    __align__(16) float q[32];
    const float4* qr = (const float4*)(g_q + ((size_t)bh * 1024 + i) * 32);
    #pragma unroll
    for (int j = 0; j < 8; j++) ((float4*)q)[j] = qr[j];
    const float* abg = g_ab + (size_t)h * 49 * 1024 + i;  // [h][a][i] layout, coalesced per a

    float s[49];
    float m = -1e30f;
    #pragma unroll
    for (int a = 0; a < 49; a++) {
        float dot = 0.f;
        #pragma unroll
        for (int d = 0; d < 32; d++) dot += q[d] * ahs[a * 32 + d];
        s[a] = dot * SCALE + abg[(size_t)a * 1024];
        m = fmaxf(m, s[a]);
    }
    float sum = 0.f;
    #pragma unroll
    for (int a = 0; a < 49; a++) {
        s[a] = __expf(s[a] - m);
        sum += s[a];
    }
    float inv = 1.f / sum;
    __align__(16) float out[32] = {};
    #pragma unroll
    for (int a = 0; a < 49; a++) {
        #pragma unroll
        for (int d = 0; d < 32; d++) out[d] += s[a] * avs[a * 32 + d];
    }

    // depthwise 3x3 on v (zero-padded) + bias, folded into same output
    const float* vrow0 = vsm + warp * VROW + lane * 33;  // (row y-1, x-1) base
    #pragma unroll
    for (int d = 0; d < 32; d++) {
        float sdw = bsm[d];
        #pragma unroll
        for (int dy = 0; dy < 3; dy++) {
            const float* vr = vrow0 + dy * VROW + d;
            const float* wk = wsm + d * 9 + dy * 3;
            sdw += vr[0] * wk[0] + vr[33] * wk[1] + vr[66] * wk[2];
        }
        out[d] = out[d] * inv + sdw;
    }

    float* dst = g_attn + ((size_t)(b_ * 1024 + i) * 256) + h * 32;
    #pragma unroll
    for (int j = 0; j < 8; j++) ((float4*)dst)[j] = ((const float4*)out)[j];
}

// ---------------- launch ------------------------------------------------------
// ORDER NOTE: launch #4 is what ncu (-s 5 -c 1) captures — agent_attn_fused here.
extern "C" void kernel_launch(void* const* d_in, const int* in_sizes, int n_in,
                              void* d_out, int out_size) {
    const float* x      = (const float*)d_in[0];
    const float* qkv_w  = (const float*)d_in[1];
    const float* proj_w = (const float*)d_in[2];
    const float* proj_b = (const float*)d_in[3];
    const float* dwc_w  = (const float*)d_in[4];
    const float* dwc_b  = (const float*)d_in[5];
    const float* an_b   = (const float*)d_in[6];
    const float* ah_b   = (const float*)d_in[7];
    const float* aw_b   = (const float*)d_in[8];
    const float* na_b   = (const float*)d_in[9];
    const float* ha_b   = (const float*)d_in[10];
    const float* wa_b   = (const float*)d_in[11];
    float* out = (float*)d_out;

    const int attn2_smem = (1568 + 1568 + 6 * VROW + 288 + 32) * 4;
    cudaFuncSetAttribute(attn2_dwc_kernel,
                         cudaFuncAttributeMaxDynamicSharedMemorySize, attn2_smem);

    gemm_tc<true><<<dim3(6, 256), 256>>>(x, qkv_w, nullptr, nullptr);          // 1
    pool_kernel<<<(BATCH * AGENTS * CH + 255) / 256, 256>>>();                  // 2
    pb_kernel<<<(HEADS * AGENTS * NTOK + 255) / 256, 256>>>(an_b, ah_b, aw_b);  // 3
    agent_attn_fused<<<dim3(2, BATCH * HEADS), 256>>>();                        // 4 <- profiled
    ab_kernel<<<(HEADS * AGENTS * NTOK + 255) / 256, 256>>>(na_b, ha_b, wa_b);  // 5
    attn2_dwc_kernel<<<dim3(8, 256), 128, attn2_smem>>>(dwc_w, dwc_b);          // 6
    gemm_tc<false><<<dim3(2, 257), 256>>>(x, proj_w, proj_b, out);              // 7
}

// round 11
// speedup vs baseline: 1.0553x; 1.0007x over previous
#include <cuda_runtime.h>
#include <math.h>
#include <stdint.h>

#define HEADS 8
#define AGENTS 49
#define WIN 32
#define BATCH 32
#define NTOK 1024
#define CH 256
#define HD 32
#define SCALE 0.17677669529663687f  // 32^-0.5

// ---------------- scratch (device globals; no runtime allocation) -----------
__device__ float g_q[BATCH*HEADS*NTOK*HD];    // (b,h,i,d)
__device__ float g_k[BATCH*HEADS*NTOK*HD];
__device__ float g_v[BATCH*HEADS*NTOK*HD];
__device__ float g_ah[BATCH*HEADS*AGENTS*HD]; // agent tokens, head layout
__device__ float g_pb[HEADS*AGENTS*NTOK];     // agent-attn position bias [h][a][i]
__device__ float g_ab[HEADS*AGENTS*NTOK];     // q-attn position bias, TRANSPOSED [h][a][i]
__device__ float g_av[BATCH*HEADS*AGENTS*HD]; // agent_v
__device__ float g_attn[BATCH*NTOK*CH];       // attention out + dwc (b,i,c)

__constant__ int c_starts[7] = {0,4,9,13,18,22,27};
__constant__ int c_ends[7]   = {5,10,14,19,23,28,32};

// ---------------- tf32 helpers ----------------------------------------------
__device__ __forceinline__ uint32_t f2tf32(float f) {
    uint32_t r;
    asm("cvt.rna.tf32.f32 %0, %1;" : "=r"(r) : "f"(f));
    return r;
}

__device__ __forceinline__ void mma_tf32(float* c, const uint32_t* a, const uint32_t* b) {
    asm volatile(
        "mma.sync.aligned.m16n8k8.row.col.f32.tf32.tf32.f32 "
        "{%0,%1,%2,%3},{%4,%5,%6,%7},{%8,%9},{%0,%1,%2,%3};"
        : "+f"(c[0]), "+f"(c[1]), "+f"(c[2]), "+f"(c[3])
        : "r"(a[0]), "r"(a[1]), "r"(a[2]), "r"(a[3]), "r"(b[0]), "r"(b[1]));
}

// ---------------- tensor-core GEMM (tf32), BM=128 BN=128 BK=32, 256 thr ------
template<bool QKV>
__global__ __launch_bounds__(256) void gemm_tc(const float* __restrict__ x,
                                               const float* __restrict__ w,
                                               const float* __restrict__ bias,
                                               float* __restrict__ out) {
    __shared__ __align__(16) uint32_t As[128 * 36];
    __shared__ __align__(16) uint32_t Bs[128 * 36];
    const int tid = threadIdx.x;
    const int bm = blockIdx.y, bn = blockIdx.x;
    const int warp = tid >> 5, lane = tid & 31;
    const int g = lane >> 2, t = lane & 3;
    const int wm = warp >> 2, wn = warp & 3;
    const int M = QKV ? (BATCH * NTOK) : (BATCH * 1025);

    const float* aptr[4];
    const float* bptr[4];
    int soff[4];
    #pragma unroll
    for (int i = 0; i < 4; i++) {
        int j = tid + i * 256;
        int row = j >> 3;
        int col4 = (j & 7) << 2;
        soff[i] = row * 36 + col4;
        int gm = bm * 128 + row;
        if (QKV) {
            int b_ = gm >> 10, ii = gm & 1023;
            aptr[i] = x + (size_t)(b_ * 1025 + 1 + ii) * 256 + col4;
        } else {
            if (gm < M) {
                int b_ = gm / 1025, tt = gm % 1025;
                aptr[i] = (tt == 0) ? (x + (size_t)b_ * 1025 * 256 + col4)
                                    : (g_attn + (size_t)(b_ * 1024 + tt - 1) * 256 + col4);
            } else {
                aptr[i] = x + col4;
            }
        }
        bptr[i] = w + (size_t)(bn * 128 + row) * 256 + col4;
    }

    float acc[4][4][4] = {};

    for (int kc = 0; kc < 256; kc += 32) {
        #pragma unroll
        for (int i = 0; i < 4; i++) {
            float4 av = *(const float4*)(aptr[i] + kc);
            float4 bv = *(const float4*)(bptr[i] + kc);
            uint4 au = make_uint4(f2tf32(av.x), f2tf32(av.y), f2tf32(av.z), f2tf32(av.w));
            uint4 bu = make_uint4(f2tf32(bv.x), f2tf32(bv.y), f2tf32(bv.z), f2tf32(bv.w));
            *(uint4*)&As[soff[i]] = au;
            *(uint4*)&Bs[soff[i]] = bu;
        }
        __syncthreads();
        #pragma unroll
        for (int ks = 0; ks < 4; ks++) {
            const int kb = ks * 8;
            uint32_t af[4][4];
            #pragma unroll
            for (int mt = 0; mt < 4; mt++) {
                int mrow = wm * 64 + mt * 16 + g;
                af[mt][0] = As[mrow * 36 + kb + t];
                af[mt][1] = As[(mrow + 8) * 36 + kb + t];
                af[mt][2] = As[mrow * 36 + kb + t + 4];
                af[mt][3] = As[(mrow + 8) * 36 + kb + t + 4];
            }
            uint32_t bf[4][2];
            #pragma unroll
            for (int nt = 0; nt < 4; nt++) {
                int nrow = wn * 32 + nt * 8 + g;
                bf[nt][0] = Bs[nrow * 36 + kb + t];
                bf[nt][1] = Bs[nrow * 36 + kb + t + 4];
            }
            #pragma unroll
            for (int mt = 0; mt < 4; mt++)
                #pragma unroll
                for (int nt = 0; nt < 4; nt++)
                    mma_tf32(acc[mt][nt], af[mt], bf[nt]);
        }
        __syncthreads();
    }

    #pragma unroll
    for (int mt = 0; mt < 4; mt++) {
        #pragma unroll
        for (int nt = 0; nt < 4; nt++) {
            int coln = bn * 128 + wn * 32 + nt * 8 + 2 * t;
            #pragma unroll
            for (int half = 0; half < 2; half++) {
                int row = bm * 128 + wm * 64 + mt * 16 + g + half * 8;
                float v0 = acc[mt][nt][half * 2 + 0];
                float v1 = acc[mt][nt][half * 2 + 1];
                if (QKV) {
                    int b_ = row >> 10, i_ = row & 1023;
                    int tsel = coln >> 8, c_ = coln & 255;
                    int h = c_ >> 5, d = c_ & 31;
                    float* dst = (tsel == 0) ? g_q : (tsel == 1) ? g_k : g_v;
                    *(float2*)&dst[((size_t)(b_ * 8 + h) * 1024 + i_) * 32 + d] =
                        make_float2(v0, v1);
                } else {
                    if (row < M) {
                        *(float2*)&out[(size_t)row * 256 + coln] =
                            make_float2(v0 + bias[coln], v1 + bias[coln + 1]);
                    }
                }
            }
        }
    }
}

// ---------------- adaptive avg pool q -> agents ------------------------------
__global__ void pool_kernel() {
    int idx = blockIdx.x * 256 + threadIdx.x;
    if (idx >= BATCH * AGENTS * CH) return;
    int c = idx & 255;
    int a = (idx >> 8) % 49;
    int b = idx / (49 * 256);
    int ay = a / 7, ax = a % 7;
    int h = c >> 5, d = c & 31;
    const float* base = g_q + (size_t)(b * 8 + h) * 1024 * 32 + d;
    int ys = c_starts[ay], ye = c_ends[ay];
    int xs = c_starts[ax], xe = c_ends[ax];
    float s = 0.f;
    for (int y = ys; y < ye; y++)
        for (int xx = xs; xx < xe; xx++)
            s += base[(y * 32 + xx) * 32];
    s /= (float)((ye - ys) * (xe - xs));
    g_ah[((size_t)(b * 8 + h) * 49 + a) * 32 + d] = s;
}

// ---------------- bilinear 7x7 -> 32x32 (jax half-pixel == clamped bilerp) ---
__device__ __forceinline__ float bilerp7(const float* __restrict__ t, int y, int x) {
    float sy = (y + 0.5f) * 0.21875f - 0.5f;
    float sx = (x + 0.5f) * 0.21875f - 0.5f;
    sy = fminf(fmaxf(sy, 0.f), 6.f);
    sx = fminf(fmaxf(sx, 0.f), 6.f);
    int y0 = (int)sy, x0 = (int)sx;
    int y1 = min(y0 + 1, 6), x1 = min(x0 + 1, 6);
    float fy = sy - (float)y0, fx = sx - (float)x0;
    float v00 = t[y0 * 7 + x0], v01 = t[y0 * 7 + x1];
    float v10 = t[y1 * 7 + x0], v11 = t[y1 * 7 + x1];
    return (1.f - fy) * ((1.f - fx) * v00 + fx * v01)
         + fy * ((1.f - fx) * v10 + fx * v11);
}

__global__ void pb_kernel(const float* __restrict__ an,
                          const float* __restrict__ ahb,
                          const float* __restrict__ awb) {
    int idx = blockIdx.x * 256 + threadIdx.x;
    if (idx >= HEADS * AGENTS * NTOK) return;
    int x = idx & 31, y = (idx >> 5) & 31;
    int a = (idx >> 10) % 49, h = idx / (49 * 1024);
    float v = bilerp7(an + (h * 49 + a) * 49, y, x);
    v += ahb[(h * 49 + a) * 32 + y] + awb[(h * 49 + a) * 32 + x];
    g_pb[idx] = v;
}

// writes TRANSPOSED layout: g_ab[h][a][i]; h0 = head offset (split launches)
__global__ void ab_kernel(const float* __restrict__ na,
                          const float* __restrict__ hab,
                          const float* __restrict__ wab, int h0) {
    int idx = blockIdx.x * 256 + threadIdx.x;
    if (idx >= 4 * AGENTS * NTOK) return;
    int i = idx & 1023;
    int a = (idx >> 10) % 49;
    int h = h0 + idx / (49 * 1024);
    float v = bilerp7(na + (h * 49 + a) * 49, i >> 5, i & 31);
    v += hab[(h * 32 + (i >> 5)) * 49 + a] + wab[(h * 32 + (i & 31)) * 49 + a];
    g_ab[(size_t)h * 49 * 1024 + (size_t)a * 1024 + i] = v;
}

// ---------------- fused agent attention: softmax(ah@K^T*s + pb) @ V ----------
// grid (4, 256): x = agent quarter {13,12,12,12}, y = (b,h); flash online softmax
// all smem ops vectorized to LDS.128; V stored transposed [d][tok]
#define SS_PAD 132
__global__ __launch_bounds__(256) void agent_attn_fused() {
    __shared__ __align__(16) float Vt[32 * SS_PAD];   // [d][tok]
    __shared__ __align__(16) float ahs[13 * 32];
    __shared__ __align__(16) float Ss[13 * SS_PAD];   // [a][tok]
    __shared__ float m_s[13], l_s[13], scale_s[13];
    const int qx = blockIdx.x;
    const int A0 = (qx == 0) ? 0 : (13 + 12 * (qx - 1));
    const int NA = (qx == 0) ? 13 : 12;
    const int bh = blockIdx.y;
    const int tid = threadIdx.x;
    const int warp = tid >> 5, lane = tid & 31;
    const int h = bh & 7;
    for (int j = tid; j < NA * 32; j += 256) ahs[j] = g_ah[(size_t)bh * 1568 + A0 * 32 + j];
    if (tid < NA) { m_s[tid] = -1e30f; l_s[tid] = 0.f; }
    float acc[2] = {};
    const int half = tid >> 7;
    const int ii = tid & 127;
    const int nh0 = (NA + 1) >> 1;                 // agents in half 0
    const int la0 = half ? nh0 : 0;
    const int lan = half ? (NA - nh0) : nh0;
    __syncthreads();

    for (int it = 0; it < 8; it++) {
        const int i0 = it * 128;
        // load V tile TRANSPOSED: Vt[d][tok]
        {
            const float4* src = (const float4*)(g_v + ((size_t)bh * 1024 + i0) * 32);
            for (int j = tid; j < 1024; j += 256) {
                int tok = j >> 3, d4 = (j & 7) << 2;
                float4 v = src[j];
                Vt[(d4 + 0) * SS_PAD + tok] = v.x;
                Vt[(d4 + 1) * SS_PAD + tok] = v.y;
                Vt[(d4 + 2) * SS_PAD + tok] = v.z;
                Vt[(d4 + 3) * SS_PAD + tok] = v.w;
            }
        }
        // scores (float4 ahs reads)
        {
            __align__(16) float kr[32];
            const float4* krow = (const float4*)(g_k + ((size_t)bh * 1024 + i0 + ii) * 32);
            #pragma unroll
            for (int j = 0; j < 8; j++) ((float4*)kr)[j] = krow[j];
            const float* pbb = g_pb + (size_t)h * 49 * 1024 + (size_t)A0 * 1024 + i0 + ii;
            for (int la = la0; la < la0 + lan; la++) {
                const float4* ar = (const float4*)&ahs[la * 32];
                float dot = 0.f;
                #pragma unroll
                for (int j = 0; j < 8; j++) {
                    float4 a4 = ar[j];
                    float4 k4 = ((const float4*)kr)[j];
                    dot += a4.x * k4.x + a4.y * k4.y + a4.z * k4.z + a4.w * k4.w;
                }
                Ss[la * SS_PAD + ii] = dot * SCALE + pbb[(size_t)la * 1024];
            }
        }
        __syncthreads();
        // per-agent tile max -> running max + rescale factor (float4)
        {
            int a = tid >> 2, q = tid & 3;
            float tm = -1e30f;
            if (a < NA) {
                const float4* row = (const float4*)&Ss[a * SS_PAD + q * 32];
                #pragma unroll
                for (int k2 = 0; k2 < 8; k2++) {
                    float4 v = row[k2];
                    tm = fmaxf(tm, fmaxf(fmaxf(v.x, v.y), fmaxf(v.z, v.w)));
                }
            }
            tm = fmaxf(tm, __shfl_xor_sync(0xffffffffu, tm, 1));
            tm = fmaxf(tm, __shfl_xor_sync(0xffffffffu, tm, 2));
            if (a < NA && q == 0) {
                float mo = m_s[a];
                float mn = fmaxf(mo, tm);
                scale_s[a] = __expf(mo - mn);
                m_s[a] = mn;
            }
        }
        __syncthreads();
        // exp in place + per-agent sum (float4)
        {
            int a = tid >> 2, q = tid & 3;
            float ts = 0.f;
            if (a < NA) {
                float mm = m_s[a];
                float4* row = (float4*)&Ss[a * SS_PAD + q * 32];
                #pragma unroll
                for (int k2 = 0; k2 < 8; k2++) {
                    float4 v = row[k2];
                    v.x = __expf(v.x - mm); v.y = __expf(v.y - mm);
                    v.z = __expf(v.z - mm); v.w = __expf(v.w - mm);
                    row[k2] = v;
                    ts += v.x + v.y + v.z + v.w;
                }
            }
            ts += __shfl_xor_sync(0xffffffffu, ts, 1);
            ts += __shfl_xor_sync(0xffffffffu, ts, 2);
            if (a < NA && q == 0) l_s[a] = l_s[a] * scale_s[a] + ts;
        }
        __syncthreads();
        // P @ V accumulate: warp owns agents {warp, warp+8}, lane owns d
        {
            #pragma unroll
            for (int r = 0; r < 2; r++) {
                int a = warp + r * 8;
                if (a < NA) acc[r] *= scale_s[a];
            }
            const float4* vrow = (const float4*)&Vt[lane * SS_PAD];
            #pragma unroll 4
            for (int grp = 0; grp < 32; grp++) {
                float4 v = vrow[grp];
                #pragma unroll
                for (int r = 0; r < 2; r++) {
                    int a = warp + r * 8;
                    if (a < NA) {
                        float4 s4 = *(const float4*)&Ss[a * SS_PAD + grp * 4];
                        acc[r] += s4.x * v.x + s4.y * v.y + s4.z * v.z + s4.w * v.w;
                    }
                }
            }
        }
        __syncthreads();
    }

    #pragma unroll
    for (int r = 0; r < 2; r++) {
        int a = warp + r * 8;
        if (a < NA)
            g_av[(size_t)bh * 1568 + (A0 + a) * 32 + lane] = acc[r] / l_s[a];
    }
}

// ---------------- fused q-attn + depthwise conv ------------------------------
#define VROW (34 * 33)
__global__ __launch_bounds__(128) void attn2_dwc_kernel(const float* __restrict__ dwc_w,
                                                        const float* __restrict__ dwc_b) {
    extern __shared__ __align__(16) float sm[];
    float* ahs = sm;
    float* avs = ahs + 1568;
    float* vsm = avs + 1568;
    float* wsm = vsm + 6 * VROW;
    float* bsm = wsm + 288;

    const int bh = blockIdx.y, itile = blockIdx.x, tid = threadIdx.x;
    const int h = bh & 7, b_ = bh >> 3;
    const int i0 = itile * 128;
    const int y0 = itile * 4;
    const int warp = tid >> 5, lane = tid & 31;

    for (int j = tid; j < 1568; j += 128) {
        ahs[j] = g_ah[(size_t)bh * 1568 + j];
        avs[j] = g_av[(size_t)bh * 1568 + j];
    }
    for (int j = tid; j < 288; j += 128) wsm[j] = dwc_w[(h * 32) * 9 + j];
    if (tid < 32) bsm[tid] = dwc_b[h * 32 + tid];
    for (int j = tid; j < 6 * VROW; j += 128) vsm[j] = 0.f;
    __syncthreads();

    for (int j = tid; j < 6 * 1024; j += 128) {
        int row = j >> 10;
        int rem = j & 1023;
        int x = rem >> 5, d = rem & 31;
        int gy = y0 - 1 + row;
        if (gy >= 0 && gy < 32)
            vsm[row * VROW + (x + 1) * 33 + d] =
                g_v[((size_t)bh * 1024 + gy * 32 + x) * 32 + d];
    }
    __syncthreads();

    const int i = i0 + tid;
    __align__(16) float q[32];
    const float4* qr = (const float4*)(g_q + ((size_t)bh * 1024 + i) * 32);
    #pragma unroll
    for (int j = 0; j < 8; j++) ((float4*)q)[j] = qr[j];
    const float* abg = g_ab + (size_t)h * 49 * 1024 + i;

    float s[49];
    float m = -1e30f;
    #pragma unroll
    for (int a = 0; a < 49; a++) {
        float dot = 0.f;
        #pragma unroll
        for (int d = 0; d < 32; d++) dot += q[d] * ahs[a * 32 + d];
        s[a] = dot * SCALE + abg[(size_t)a * 1024];
        m = fmaxf(m, s[a]);
    }
    float sum = 0.f;
    #pragma unroll
    for (int a = 0; a < 49; a++) {
        s[a] = __expf(s[a] - m);
        sum += s[a];
    }
    float inv = 1.f / sum;
    __align__(16) float out[32] = {};
    #pragma unroll
    for (int a = 0; a < 49; a++) {
        #pragma unroll
        for (int d = 0; d < 32; d++) out[d] += s[a] * avs[a * 32 + d];
    }

    const float* vrow0 = vsm + warp * VROW + lane * 33;
    #pragma unroll
    for (int d = 0; d < 32; d++) {
        float sdw = bsm[d];
        #pragma unroll
        for (int dy = 0; dy < 3; dy++) {
            const float* vr = vrow0 + dy * VROW + d;
            const float* wk = wsm + d * 9 + dy * 3;
            sdw += vr[0] * wk[0] + vr[33] * wk[1] + vr[66] * wk[2];
        }
        out[d] = out[d] * inv + sdw;
    }

    float* dst = g_attn + ((size_t)(b_ * 1024 + i) * 256) + h * 32;
    #pragma unroll
    for (int j = 0; j < 8; j++) ((float4*)dst)[j] = ((const float4*)out)[j];
}

// ---------------- launch ------------------------------------------------------
// ORDER NOTE: launch #4 is what ncu captures — gemm_tc<true> (qkv) this round.
extern "C" void kernel_launch(void* const* d_in, const int* in_sizes, int n_in,
                              void* d_out, int out_size) {
    const float* x      = (const float*)d_in[0];
    const float* qkv_w  = (const float*)d_in[1];
    const float* proj_w = (const float*)d_in[2];
    const float* proj_b = (const float*)d_in[3];
    const float* dwc_w  = (const float*)d_in[4];
    const float* dwc_b  = (const float*)d_in[5];
    const float* an_b   = (const float*)d_in[6];
    const float* ah_b   = (const float*)d_in[7];
    const float* aw_b   = (const float*)d_in[8];
    const float* na_b   = (const float*)d_in[9];
    const float* ha_b   = (const float*)d_in[10];
    const float* wa_b   = (const float*)d_in[11];
    float* out = (float*)d_out;

    const int attn2_smem = (1568 + 1568 + 6 * VROW + 288 + 32) * 4;
    cudaFuncSetAttribute(attn2_dwc_kernel,
                         cudaFuncAttributeMaxDynamicSharedMemorySize, attn2_smem);

    const int abHalf = (4 * AGENTS * NTOK + 255) / 256;
    pb_kernel<<<(HEADS * AGENTS * NTOK + 255) / 256, 256>>>(an_b, ah_b, aw_b);  // 1
    ab_kernel<<<abHalf, 256>>>(na_b, ha_b, wa_b, 0);                            // 2
    ab_kernel<<<abHalf, 256>>>(na_b, ha_b, wa_b, 4);                            // 3
    gemm_tc<true><<<dim3(6, 256), 256>>>(x, qkv_w, nullptr, nullptr);           // 4 <- profiled
    pool_kernel<<<(BATCH * AGENTS * CH + 255) / 256, 256>>>();                   // 5
    agent_attn_fused<<<dim3(4, BATCH * HEADS), 256>>>();                         // 6
    attn2_dwc_kernel<<<dim3(8, 256), 128, attn2_smem>>>(dwc_w, dwc_b);           // 7
    gemm_tc<false><<<dim3(2, 257), 256>>>(x, proj_w, proj_b, out);               // 8
}